// round 1
// baseline (speedup 1.0000x reference)
#include <cuda_runtime.h>
#include <cuda_bf16.h>
#include <cstdint>

#define N_NODES 100000
#define N_HE    30000
#define N_INC   300000
#define IN_CH   128
#define HID     256
#define OUT_CH  128
#define BN_EPS  1e-5f

// ---------------- device scratch (allocation-free) ----------------
__device__ float g_X1[(size_t)N_NODES * HID];   // GEMM out / AGG (reused)
__device__ float g_H [(size_t)N_NODES * HID];   // BN output (next layer input)
__device__ float g_HE[(size_t)N_HE   * HID];    // hyperedge features

__device__ int g_nd_cnt[N_NODES];
__device__ int g_he_cnt[N_HE];
__device__ int g_nd_off[N_NODES + 1];
__device__ int g_he_off[N_HE + 1];
__device__ int g_nd_hes[N_INC];
__device__ int g_he_nodes[N_INC];

__device__ float g_sum[HID];
__device__ float g_sumsq[HID];

// ---------------- CSR build ----------------
__global__ void k_hist(const int* __restrict__ node_idx, const int* __restrict__ he_idx) {
    int i = blockIdx.x * blockDim.x + threadIdx.x;
    if (i < N_INC) {
        atomicAdd(&g_nd_cnt[node_idx[i]], 1);
        atomicAdd(&g_he_cnt[he_idx[i]], 1);
    }
}

// single-block exclusive scan (1024 threads), cnt -> off, off[n] = total
__global__ void k_scan(const int* __restrict__ cnt, int* __restrict__ off, int n) {
    __shared__ int warp_sums[32];
    __shared__ int s_carry;
    int tid = threadIdx.x, lane = tid & 31, wid = tid >> 5;
    if (tid == 0) s_carry = 0;
    __syncthreads();
    for (int base = 0; base < n; base += 1024) {
        int v = (base + tid < n) ? cnt[base + tid] : 0;
        int x = v;
#pragma unroll
        for (int o = 1; o < 32; o <<= 1) {
            int t = __shfl_up_sync(0xFFFFFFFFu, x, o);
            if (lane >= o) x += t;
        }
        if (lane == 31) warp_sums[wid] = x;
        __syncthreads();
        if (wid == 0) {
            int w = warp_sums[lane];
            int y = w;
#pragma unroll
            for (int o = 1; o < 32; o <<= 1) {
                int t = __shfl_up_sync(0xFFFFFFFFu, y, o);
                if (lane >= o) y += t;
            }
            warp_sums[lane] = y - w;   // exclusive warp prefix
        }
        __syncthreads();
        int incl = x + warp_sums[wid];
        if (base + tid < n) off[base + tid] = s_carry + incl - v;
        __syncthreads();
        if (tid == 1023) s_carry += incl;
        __syncthreads();
    }
    if (threadIdx.x == 0) off[n] = s_carry;
}

__global__ void k_scatter(const int* __restrict__ node_idx, const int* __restrict__ he_idx) {
    int i = blockIdx.x * blockDim.x + threadIdx.x;
    if (i < N_INC) {
        int n = node_idx[i], e = he_idx[i];
        int p = atomicAdd(&g_he_cnt[e], 1);
        g_he_nodes[g_he_off[e] + p] = n;
        int q = atomicAdd(&g_nd_cnt[n], 1);
        g_nd_hes[g_nd_off[n] + q] = e;
    }
}

// ---------------- SGEMM: C[M,N] = A[M,K] @ B[K,N], 128x128 tile, 8x8 microtile ----------------
__global__ __launch_bounds__(256) void sgemm128(
    const float* __restrict__ A, const float* __restrict__ B,
    float* __restrict__ C, int M, int K, int N)
{
    __shared__ float As[8][129];
    __shared__ float Bs[8][128];
    const int tid = threadIdx.x;
    const int tx = tid % 16;
    const int ty = tid / 16;
    const int row0 = blockIdx.y * 128;
    const int col0 = blockIdx.x * 128;

    float acc[8][8];
#pragma unroll
    for (int i = 0; i < 8; i++)
#pragma unroll
        for (int j = 0; j < 8; j++) acc[i][j] = 0.f;

    const int a_m = (tid * 4) >> 3;   // 0..127
    const int a_k = (tid * 4) & 7;    // 0 or 4
    const int b_k = (tid * 4) >> 7;   // 0..7
    const int b_n = (tid * 4) & 127;

    for (int k0 = 0; k0 < K; k0 += 8) {
        float4 av;
        if (row0 + a_m < M)
            av = *reinterpret_cast<const float4*>(A + (size_t)(row0 + a_m) * K + k0 + a_k);
        else
            av = make_float4(0.f, 0.f, 0.f, 0.f);
        As[a_k + 0][a_m] = av.x;
        As[a_k + 1][a_m] = av.y;
        As[a_k + 2][a_m] = av.z;
        As[a_k + 3][a_m] = av.w;

        float4 bv = *reinterpret_cast<const float4*>(B + (size_t)(k0 + b_k) * N + col0 + b_n);
        *reinterpret_cast<float4*>(&Bs[b_k][b_n]) = bv;
        __syncthreads();

#pragma unroll
        for (int kk = 0; kk < 8; kk++) {
            float a[8], b[8];
#pragma unroll
            for (int i = 0; i < 8; i++) a[i] = As[kk][ty * 8 + i];
#pragma unroll
            for (int j = 0; j < 8; j++) b[j] = Bs[kk][tx * 8 + j];
#pragma unroll
            for (int i = 0; i < 8; i++)
#pragma unroll
                for (int j = 0; j < 8; j++) acc[i][j] = fmaf(a[i], b[j], acc[i][j]);
        }
        __syncthreads();
    }

#pragma unroll
    for (int i = 0; i < 8; i++) {
        int r = row0 + ty * 8 + i;
        if (r < M) {
            float* Cr = C + (size_t)r * N + col0 + tx * 8;
#pragma unroll
            for (int j = 0; j < 8; j += 4) {
                float4 v = make_float4(acc[i][j], acc[i][j + 1], acc[i][j + 2], acc[i][j + 3]);
                *reinterpret_cast<float4*>(Cr + j) = v;
            }
        }
    }
}

// ---------------- aggregation ----------------
// one block per hyperedge, F/4 threads (float4 per thread)
__global__ void k_he_gather(const float* __restrict__ X, float* __restrict__ HE, int F4) {
    int e = blockIdx.x;
    int f = threadIdx.x;
    int s = g_he_off[e], t = g_he_off[e + 1];
    float4 acc = make_float4(0.f, 0.f, 0.f, 0.f);
    for (int j = s; j < t; j++) {
        int n = g_he_nodes[j];
        float4 v = reinterpret_cast<const float4*>(X)[(size_t)n * F4 + f];
        acc.x += v.x; acc.y += v.y; acc.z += v.z; acc.w += v.w;
    }
    float inv = (t > s) ? 1.0f / (float)(t - s) : 0.f;
    acc.x *= inv; acc.y *= inv; acc.z *= inv; acc.w *= inv;
    reinterpret_cast<float4*>(HE)[(size_t)e * F4 + f] = acc;
}

// one block per node, F/4 threads: out = relu(Dinv * sum + bias)
__global__ void k_node_gather(const float* __restrict__ HE, const float* __restrict__ bias,
                              float* __restrict__ OUT, int F4) {
    int n = blockIdx.x;
    int f = threadIdx.x;
    int s = g_nd_off[n], t = g_nd_off[n + 1];
    float4 acc = make_float4(0.f, 0.f, 0.f, 0.f);
    for (int j = s; j < t; j++) {
        int e = g_nd_hes[j];
        float4 v = reinterpret_cast<const float4*>(HE)[(size_t)e * F4 + f];
        acc.x += v.x; acc.y += v.y; acc.z += v.z; acc.w += v.w;
    }
    float inv = (t > s) ? 1.0f / (float)(t - s) : 0.f;
    float4 b4 = reinterpret_cast<const float4*>(bias)[f];
    acc.x = fmaxf(fmaf(acc.x, inv, b4.x), 0.f);
    acc.y = fmaxf(fmaf(acc.y, inv, b4.y), 0.f);
    acc.z = fmaxf(fmaf(acc.z, inv, b4.z), 0.f);
    acc.w = fmaxf(fmaf(acc.w, inv, b4.w), 0.f);
    reinterpret_cast<float4*>(OUT)[(size_t)n * F4 + f] = acc;
}

// ---------------- batch norm (F = HID = 256) ----------------
#define BN_ROWS_PER_BLOCK 250
__global__ void k_bn_stats(const float* __restrict__ X) {
    int f = threadIdx.x;                    // 256 threads
    int r0 = blockIdx.x * BN_ROWS_PER_BLOCK;
    float s = 0.f, ss = 0.f;
    for (int r = 0; r < BN_ROWS_PER_BLOCK; r++) {
        int row = r0 + r;
        if (row >= N_NODES) break;
        float v = X[(size_t)row * HID + f];
        s += v;
        ss += v * v;
    }
    atomicAdd(&g_sum[f], s);
    atomicAdd(&g_sumsq[f], ss);
}

__global__ void k_bn_apply(const float* __restrict__ X, float* __restrict__ Y,
                           const float* __restrict__ g, const float* __restrict__ be) {
    int idx = blockIdx.x * blockDim.x + threadIdx.x;   // over N*HID/4
    if (idx >= N_NODES * (HID / 4)) return;
    int f4 = idx & (HID / 4 - 1);
    float4 sm = reinterpret_cast<const float4*>(g_sum)[f4];
    float4 sq = reinterpret_cast<const float4*>(g_sumsq)[f4];
    float4 gg = reinterpret_cast<const float4*>(g)[f4];
    float4 bb = reinterpret_cast<const float4*>(be)[f4];
    const float invN = 1.0f / (float)N_NODES;
    float4 x = reinterpret_cast<const float4*>(X)[idx];
    float4 y;
    {
        float m = sm.x * invN; float v = sq.x * invN - m * m;
        float sc = gg.x * rsqrtf(v + BN_EPS); y.x = (x.x - m) * sc + bb.x;
    }
    {
        float m = sm.y * invN; float v = sq.y * invN - m * m;
        float sc = gg.y * rsqrtf(v + BN_EPS); y.y = (x.y - m) * sc + bb.y;
    }
    {
        float m = sm.z * invN; float v = sq.z * invN - m * m;
        float sc = gg.z * rsqrtf(v + BN_EPS); y.z = (x.z - m) * sc + bb.z;
    }
    {
        float m = sm.w * invN; float v = sq.w * invN - m * m;
        float sc = gg.w * rsqrtf(v + BN_EPS); y.w = (x.w - m) * sc + bb.w;
    }
    reinterpret_cast<float4*>(Y)[idx] = y;
}

// ---------------- launch ----------------
extern "C" void kernel_launch(void* const* d_in, const int* in_sizes, int n_in,
                              void* d_out, int out_size) {
    const float* x    = (const float*)d_in[0];
    const int*   edge = (const int*)d_in[1];
    const int*   node_idx = edge;
    const int*   he_idx   = edge + N_INC;
    const float* W1 = (const float*)d_in[2];
    const float* b1 = (const float*)d_in[3];
    const float* g1 = (const float*)d_in[4];
    const float* be1 = (const float*)d_in[5];
    const float* W2 = (const float*)d_in[6];
    const float* b2 = (const float*)d_in[7];
    const float* g2 = (const float*)d_in[8];
    const float* be2 = (const float*)d_in[9];
    const float* W3 = (const float*)d_in[10];
    const float* b3 = (const float*)d_in[11];
    float* out = (float*)d_out;

    void *p_X1, *p_H, *p_HE, *p_nd_cnt, *p_he_cnt, *p_sum, *p_sumsq;
    cudaGetSymbolAddress(&p_X1, g_X1);
    cudaGetSymbolAddress(&p_H, g_H);
    cudaGetSymbolAddress(&p_HE, g_HE);
    cudaGetSymbolAddress(&p_nd_cnt, g_nd_cnt);
    cudaGetSymbolAddress(&p_he_cnt, g_he_cnt);
    cudaGetSymbolAddress(&p_sum, g_sum);
    cudaGetSymbolAddress(&p_sumsq, g_sumsq);
    float* X1 = (float*)p_X1;
    float* H  = (float*)p_H;
    float* HE = (float*)p_HE;

    void *p_nd_off, *p_he_off;
    cudaGetSymbolAddress(&p_nd_off, g_nd_off);
    cudaGetSymbolAddress(&p_he_off, g_he_off);

    // ---- CSR build (per replay; deterministic work) ----
    cudaMemsetAsync(p_nd_cnt, 0, N_NODES * sizeof(int));
    cudaMemsetAsync(p_he_cnt, 0, N_HE * sizeof(int));
    k_hist<<<(N_INC + 255) / 256, 256>>>(node_idx, he_idx);
    k_scan<<<1, 1024>>>((const int*)p_nd_cnt, (int*)p_nd_off, N_NODES);
    k_scan<<<1, 1024>>>((const int*)p_he_cnt, (int*)p_he_off, N_HE);
    cudaMemsetAsync(p_nd_cnt, 0, N_NODES * sizeof(int));
    cudaMemsetAsync(p_he_cnt, 0, N_HE * sizeof(int));
    k_scatter<<<(N_INC + 255) / 256, 256>>>(node_idx, he_idx);

    const int bn_grid = (N_NODES + BN_ROWS_PER_BLOCK - 1) / BN_ROWS_PER_BLOCK;
    const int apply_grid = (N_NODES * (HID / 4) + 255) / 256;

    // ---- layer 1: x[100k,128] @ W1[128,256] ----
    {
        dim3 grid(HID / 128, (N_NODES + 127) / 128);
        sgemm128<<<grid, 256>>>(x, W1, X1, N_NODES, IN_CH, HID);
        k_he_gather<<<N_HE, HID / 4>>>(X1, HE, HID / 4);
        k_node_gather<<<N_NODES, HID / 4>>>(HE, b1, X1, HID / 4);  // AGG in X1
        cudaMemsetAsync(p_sum, 0, HID * sizeof(float));
        cudaMemsetAsync(p_sumsq, 0, HID * sizeof(float));
        k_bn_stats<<<bn_grid, HID>>>(X1);
        k_bn_apply<<<apply_grid, 256>>>(X1, H, g1, be1);
    }
    // ---- layer 2: H[100k,256] @ W2[256,256] ----
    {
        dim3 grid(HID / 128, (N_NODES + 127) / 128);
        sgemm128<<<grid, 256>>>(H, W2, X1, N_NODES, HID, HID);
        k_he_gather<<<N_HE, HID / 4>>>(X1, HE, HID / 4);
        k_node_gather<<<N_NODES, HID / 4>>>(HE, b2, X1, HID / 4);
        cudaMemsetAsync(p_sum, 0, HID * sizeof(float));
        cudaMemsetAsync(p_sumsq, 0, HID * sizeof(float));
        k_bn_stats<<<bn_grid, HID>>>(X1);
        k_bn_apply<<<apply_grid, 256>>>(X1, H, g2, be2);
    }
    // ---- layer 3: H[100k,256] @ W3[256,128], relu -> out ----
    {
        dim3 grid(OUT_CH / 128, (N_NODES + 127) / 128);
        sgemm128<<<grid, 256>>>(H, W3, X1, N_NODES, HID, OUT_CH);
        k_he_gather<<<N_HE, OUT_CH / 4>>>(X1, HE, OUT_CH / 4);
        k_node_gather<<<N_NODES, OUT_CH / 4>>>(HE, b3, out, OUT_CH / 4);
    }
}

// round 3
// speedup vs baseline: 1.4049x; 1.4049x over previous
#include <cuda_runtime.h>
#include <cuda_bf16.h>
#include <cstdint>

#define N_NODES 100000
#define N_HE    30000
#define N_INC   300000
#define IN_CH   128
#define HID     256
#define OUT_CH  128
#define BN_EPS  1e-5f

// ---------------- device scratch (allocation-free) ----------------
__device__ float g_X1[(size_t)N_NODES * HID];   // GEMM out / AGG (reused)
__device__ float g_H [(size_t)N_NODES * HID];   // BN output (next layer input)
__device__ float g_HE[(size_t)N_HE   * HID];    // hyperedge features
__device__ __nv_bfloat16 g_Xs[(size_t)N_NODES * 3 * HID]; // split activations [M, 3K]
__device__ __nv_bfloat16 g_Ws[(size_t)HID * 3 * HID];     // split weights [N, 3K] (transposed)

__device__ int g_nd_cnt[N_NODES];
__device__ int g_he_cnt[N_HE];
__device__ int g_nd_off[N_NODES + 1];
__device__ int g_he_off[N_HE + 1];
__device__ int g_nd_hes[N_INC];
__device__ int g_he_nodes[N_INC];

__device__ float g_sum[HID];
__device__ float g_sumsq[HID];

// ---------------- helpers ----------------
__device__ __forceinline__ uint32_t smem_to_u32(const void* p) {
    uint32_t a;
    asm("{ .reg .u64 t; cvta.to.shared.u64 t, %1; cvt.u32.u64 %0, t; }" : "=r"(a) : "l"(p));
    return a;
}
#define SWZ(off) ((off) ^ (((off) >> 3) & 0x70))

__device__ __forceinline__ void cp_async16(uint32_t dst, const void* src) {
    asm volatile("cp.async.cg.shared.global [%0], [%1], 16;" :: "r"(dst), "l"(src) : "memory");
}

// ---------------- CSR build ----------------
__global__ void k_hist(const int* __restrict__ node_idx, const int* __restrict__ he_idx) {
    int i = blockIdx.x * blockDim.x + threadIdx.x;
    if (i < N_INC) {
        atomicAdd(&g_nd_cnt[node_idx[i]], 1);
        atomicAdd(&g_he_cnt[he_idx[i]], 1);
    }
}

__global__ void k_scan(const int* __restrict__ cnt, int* __restrict__ off, int n) {
    __shared__ int warp_sums[32];
    __shared__ int s_carry;
    int tid = threadIdx.x, lane = tid & 31, wid = tid >> 5;
    if (tid == 0) s_carry = 0;
    __syncthreads();
    for (int base = 0; base < n; base += 1024) {
        int v = (base + tid < n) ? cnt[base + tid] : 0;
        int x = v;
#pragma unroll
        for (int o = 1; o < 32; o <<= 1) {
            int t = __shfl_up_sync(0xFFFFFFFFu, x, o);
            if (lane >= o) x += t;
        }
        if (lane == 31) warp_sums[wid] = x;
        __syncthreads();
        if (wid == 0) {
            int w = warp_sums[lane];
            int y = w;
#pragma unroll
            for (int o = 1; o < 32; o <<= 1) {
                int t = __shfl_up_sync(0xFFFFFFFFu, y, o);
                if (lane >= o) y += t;
            }
            warp_sums[lane] = y - w;
        }
        __syncthreads();
        int incl = x + warp_sums[wid];
        if (base + tid < n) off[base + tid] = s_carry + incl - v;
        __syncthreads();
        if (tid == 1023) s_carry += incl;
        __syncthreads();
    }
    if (threadIdx.x == 0) off[n] = s_carry;
}

__global__ void k_scatter(const int* __restrict__ node_idx, const int* __restrict__ he_idx) {
    int i = blockIdx.x * blockDim.x + threadIdx.x;
    if (i < N_INC) {
        int n = node_idx[i], e = he_idx[i];
        int p = atomicAdd(&g_he_cnt[e], 1);
        g_he_nodes[g_he_off[e] + p] = n;
        int q = atomicAdd(&g_nd_cnt[n], 1);
        g_nd_hes[g_nd_off[n] + q] = e;
    }
}

// ---------------- fp32 -> bf16 split kernels ----------------
// Xs row layout: [hi(F) | lo(F) | hi(F)]
__global__ void k_split_X(const float* __restrict__ X, __nv_bfloat16* __restrict__ Xs, int F) {
    int i = blockIdx.x * blockDim.x + threadIdx.x;
    int half = F >> 1;
    int total = N_NODES * half;
    if (i >= total) return;
    int row = i / half, c2 = i - row * half;
    float2 v = reinterpret_cast<const float2*>(X)[i];
    __nv_bfloat16 hx = __float2bfloat16(v.x);
    __nv_bfloat16 hy = __float2bfloat16(v.y);
    __nv_bfloat16 lx = __float2bfloat16(v.x - __bfloat162float(hx));
    __nv_bfloat16 ly = __float2bfloat16(v.y - __bfloat162float(hy));
    __nv_bfloat162 h2; h2.x = hx; h2.y = hy;
    __nv_bfloat162 l2; l2.x = lx; l2.y = ly;
    __nv_bfloat162* O = reinterpret_cast<__nv_bfloat162*>(Xs) + (size_t)row * (3 * half);
    O[c2] = h2;
    O[half + c2] = l2;
    O[2 * half + c2] = h2;
}

// W [K,N] fp32 -> Ws [N, 3K] bf16 (transposed), row layout [hi(K) | hi(K) | lo(K)]
__global__ void k_split_W(const float* __restrict__ W, __nv_bfloat16* __restrict__ Ws, int K, int N) {
    int i = blockIdx.x * blockDim.x + threadIdx.x;
    if (i >= K * N) return;
    int k = i / N, n = i - k * N;
    float v = W[i];
    __nv_bfloat16 h = __float2bfloat16(v);
    __nv_bfloat16 l = __float2bfloat16(v - __bfloat162float(h));
    __nv_bfloat16* O = Ws + (size_t)n * 3 * K;
    O[k] = h;
    O[K + k] = h;
    O[2 * K + k] = l;
}

// ---------------- HMMA bf16 GEMM: C[M,N] = A[M,Kt] @ B[N,Kt]^T ----------------
// 128x128 CTA tile (grid: N/128 x ceil(M/128)), 8 warps, warp tile 32x64.
// K-chunks of 64 double-buffered via cp.async, SW128-swizzled smem, ldmatrix+mma.sync.
__global__ void __launch_bounds__(256, 2)
gemm_bf16_mma(const __nv_bfloat16* __restrict__ A, const __nv_bfloat16* __restrict__ B,
              float* __restrict__ C, int M, int Kt, int N,
              const float* __restrict__ bias, int do_relu)
{
    extern __shared__ char smc[];
    const uint32_t sbase = smem_to_u32(smc);
    const int tid  = threadIdx.x;
    const int lane = tid & 31;
    const int wid  = tid >> 5;
    const int wm   = wid >> 1;       // 0..3 -> 32-row slice
    const int wn   = wid & 1;        // 0..1 -> 64-col slice
    const int row0  = blockIdx.y * 128;
    const int nblk0 = blockIdx.x * 128;

    float acc[2][8][4];
#pragma unroll
    for (int i = 0; i < 2; i++)
#pragma unroll
        for (int j = 0; j < 8; j++)
#pragma unroll
            for (int k = 0; k < 4; k++) acc[i][j][k] = 0.f;

    // lane-relative logical byte offsets inside a [128 rows x 128B] tile
    uint32_t a_off[2], b_off[4];
#pragma unroll
    for (int mf = 0; mf < 2; mf++)
        a_off[mf] = (uint32_t)((wm * 32 + mf * 16 + (lane & 15)) * 128 + (lane >> 4) * 16);
#pragma unroll
    for (int nf4 = 0; nf4 < 4; nf4++)
        b_off[nf4] = (uint32_t)((wn * 64 + nf4 * 16 + (lane & 7) + ((lane >> 4) & 1) * 8) * 128
                                + ((lane >> 3) & 1) * 16);

    const int nch = Kt >> 6;

    auto load_chunk = [&](int c, int buf) {
        const __nv_bfloat16* Ag = A + (size_t)row0 * Kt + c * 64;
        const __nv_bfloat16* Bg = B + (size_t)nblk0 * Kt + c * 64;
        uint32_t ab = sbase + buf * 16384;
        uint32_t bb = sbase + 32768 + buf * 16384;
#pragma unroll
        for (int it = 0; it < 8; it++) {
            int i = tid + it * 256;            // 0..2047
            if (i < 1024) {                    // A tile: 128 rows x 8 16B-chunks
                int r = i >> 3, q = i & 7;
                if (row0 + r < M)
                    cp_async16(ab + SWZ((uint32_t)(r * 128 + q * 16)),
                               Ag + (size_t)r * Kt + q * 8);
            } else {                           // B tile
                int j = i - 1024;
                int r = j >> 3, q = j & 7;
                cp_async16(bb + SWZ((uint32_t)(r * 128 + q * 16)),
                           Bg + (size_t)r * Kt + q * 8);
            }
        }
        asm volatile("cp.async.commit_group;" ::: "memory");
    };

    load_chunk(0, 0);

    for (int c = 0; c < nch; c++) {
        int buf = c & 1;
        if (c + 1 < nch) {
            load_chunk(c + 1, (c + 1) & 1);
            asm volatile("cp.async.wait_group 1;" ::: "memory");
        } else {
            asm volatile("cp.async.wait_group 0;" ::: "memory");
        }
        __syncthreads();

        uint32_t ab = sbase + buf * 16384;
        uint32_t bb = sbase + 32768 + buf * 16384;
#pragma unroll
        for (int k16 = 0; k16 < 4; k16++) {
            uint32_t a[2][4], b[4][4];
#pragma unroll
            for (int mf = 0; mf < 2; mf++) {
                uint32_t addr = ab + SWZ(a_off[mf] + (uint32_t)(k16 * 32));
                asm volatile("ldmatrix.sync.aligned.m8n8.x4.shared.b16 {%0,%1,%2,%3}, [%4];"
                             : "=r"(a[mf][0]), "=r"(a[mf][1]), "=r"(a[mf][2]), "=r"(a[mf][3])
                             : "r"(addr));
            }
#pragma unroll
            for (int nf4 = 0; nf4 < 4; nf4++) {
                uint32_t addr = bb + SWZ(b_off[nf4] + (uint32_t)(k16 * 32));
                asm volatile("ldmatrix.sync.aligned.m8n8.x4.shared.b16 {%0,%1,%2,%3}, [%4];"
                             : "=r"(b[nf4][0]), "=r"(b[nf4][1]), "=r"(b[nf4][2]), "=r"(b[nf4][3])
                             : "r"(addr));
            }
#pragma unroll
            for (int mf = 0; mf < 2; mf++)
#pragma unroll
                for (int nf = 0; nf < 8; nf++) {
                    asm volatile(
                        "mma.sync.aligned.m16n8k16.row.col.f32.bf16.bf16.f32 "
                        "{%0,%1,%2,%3}, {%4,%5,%6,%7}, {%8,%9}, {%0,%1,%2,%3};"
                        : "+f"(acc[mf][nf][0]), "+f"(acc[mf][nf][1]),
                          "+f"(acc[mf][nf][2]), "+f"(acc[mf][nf][3])
                        : "r"(a[mf][0]), "r"(a[mf][1]), "r"(a[mf][2]), "r"(a[mf][3]),
                          "r"(b[nf >> 1][(nf & 1) * 2]), "r"(b[nf >> 1][(nf & 1) * 2 + 1]));
                }
        }
        __syncthreads();
    }

    // epilogue: c0,c1 -> row lane/4, cols 2*(lane&3)+{0,1}; c2,c3 -> row+8
#pragma unroll
    for (int mf = 0; mf < 2; mf++) {
        int r0g = row0 + wm * 32 + mf * 16 + (lane >> 2);
        int r1g = r0g + 8;
#pragma unroll
        for (int nf = 0; nf < 8; nf++) {
            int col = nblk0 + wn * 64 + nf * 8 + (lane & 3) * 2;
            float2 v0 = make_float2(acc[mf][nf][0], acc[mf][nf][1]);
            float2 v1 = make_float2(acc[mf][nf][2], acc[mf][nf][3]);
            if (bias) {
                float bx = bias[col], by = bias[col + 1];
                v0.x += bx; v0.y += by;
                v1.x += bx; v1.y += by;
            }
            if (do_relu) {
                v0.x = fmaxf(v0.x, 0.f); v0.y = fmaxf(v0.y, 0.f);
                v1.x = fmaxf(v1.x, 0.f); v1.y = fmaxf(v1.y, 0.f);
            }
            if (r0g < M) *reinterpret_cast<float2*>(C + (size_t)r0g * N + col) = v0;
            if (r1g < M) *reinterpret_cast<float2*>(C + (size_t)r1g * N + col) = v1;
        }
    }
}

// ---------------- aggregation ----------------
__global__ void k_he_gather(const float* __restrict__ X, float* __restrict__ HE, int F4) {
    int e = blockIdx.x;
    int f = threadIdx.x;
    int s = g_he_off[e], t = g_he_off[e + 1];
    float4 acc = make_float4(0.f, 0.f, 0.f, 0.f);
    for (int j = s; j < t; j++) {
        int n = g_he_nodes[j];
        float4 v = reinterpret_cast<const float4*>(X)[(size_t)n * F4 + f];
        acc.x += v.x; acc.y += v.y; acc.z += v.z; acc.w += v.w;
    }
    float inv = (t > s) ? 1.0f / (float)(t - s) : 0.f;
    acc.x *= inv; acc.y *= inv; acc.z *= inv; acc.w *= inv;
    reinterpret_cast<float4*>(HE)[(size_t)e * F4 + f] = acc;
}

// bias==nullptr -> raw D^{-1} aggregation (no bias, no relu)
__global__ void k_node_gather(const float* __restrict__ HE, const float* __restrict__ bias,
                              float* __restrict__ OUT, int F4) {
    int n = blockIdx.x;
    int f = threadIdx.x;
    int s = g_nd_off[n], t = g_nd_off[n + 1];
    float4 acc = make_float4(0.f, 0.f, 0.f, 0.f);
    for (int j = s; j < t; j++) {
        int e = g_nd_hes[j];
        float4 v = reinterpret_cast<const float4*>(HE)[(size_t)e * F4 + f];
        acc.x += v.x; acc.y += v.y; acc.z += v.z; acc.w += v.w;
    }
    float inv = (t > s) ? 1.0f / (float)(t - s) : 0.f;
    if (bias) {
        float4 b4 = reinterpret_cast<const float4*>(bias)[f];
        acc.x = fmaxf(fmaf(acc.x, inv, b4.x), 0.f);
        acc.y = fmaxf(fmaf(acc.y, inv, b4.y), 0.f);
        acc.z = fmaxf(fmaf(acc.z, inv, b4.z), 0.f);
        acc.w = fmaxf(fmaf(acc.w, inv, b4.w), 0.f);
    } else {
        acc.x *= inv; acc.y *= inv; acc.z *= inv; acc.w *= inv;
    }
    reinterpret_cast<float4*>(OUT)[(size_t)n * F4 + f] = acc;
}

// ---------------- batch norm (F = HID = 256) ----------------
#define BN_ROWS_PER_BLOCK 250
__global__ void k_bn_stats(const float* __restrict__ X) {
    int f = threadIdx.x;
    int r0 = blockIdx.x * BN_ROWS_PER_BLOCK;
    float s = 0.f, ss = 0.f;
    for (int r = 0; r < BN_ROWS_PER_BLOCK; r++) {
        int row = r0 + r;
        if (row >= N_NODES) break;
        float v = X[(size_t)row * HID + f];
        s += v;
        ss += v * v;
    }
    atomicAdd(&g_sum[f], s);
    atomicAdd(&g_sumsq[f], ss);
}

__global__ void k_bn_apply(const float* __restrict__ X, float* __restrict__ Y,
                           const float* __restrict__ g, const float* __restrict__ be) {
    int idx = blockIdx.x * blockDim.x + threadIdx.x;
    if (idx >= N_NODES * (HID / 4)) return;
    int f4 = idx & (HID / 4 - 1);
    float4 sm = reinterpret_cast<const float4*>(g_sum)[f4];
    float4 sq = reinterpret_cast<const float4*>(g_sumsq)[f4];
    float4 gg = reinterpret_cast<const float4*>(g)[f4];
    float4 bb = reinterpret_cast<const float4*>(be)[f4];
    const float invN = 1.0f / (float)N_NODES;
    float4 x = reinterpret_cast<const float4*>(X)[idx];
    float4 y;
    { float m = sm.x * invN; float v = sq.x * invN - m * m;
      float sc = gg.x * rsqrtf(v + BN_EPS); y.x = (x.x - m) * sc + bb.x; }
    { float m = sm.y * invN; float v = sq.y * invN - m * m;
      float sc = gg.y * rsqrtf(v + BN_EPS); y.y = (x.y - m) * sc + bb.y; }
    { float m = sm.z * invN; float v = sq.z * invN - m * m;
      float sc = gg.z * rsqrtf(v + BN_EPS); y.z = (x.z - m) * sc + bb.z; }
    { float m = sm.w * invN; float v = sq.w * invN - m * m;
      float sc = gg.w * rsqrtf(v + BN_EPS); y.w = (x.w - m) * sc + bb.w; }
    reinterpret_cast<float4*>(Y)[idx] = y;
}

// ---------------- launch ----------------
extern "C" void kernel_launch(void* const* d_in, const int* in_sizes, int n_in,
                              void* d_out, int out_size) {
    const float* x    = (const float*)d_in[0];
    const int*   edge = (const int*)d_in[1];
    const int*   node_idx = edge;
    const int*   he_idx   = edge + N_INC;
    const float* W1 = (const float*)d_in[2];
    const float* b1 = (const float*)d_in[3];
    const float* g1 = (const float*)d_in[4];
    const float* be1 = (const float*)d_in[5];
    const float* W2 = (const float*)d_in[6];
    const float* b2 = (const float*)d_in[7];
    const float* g2 = (const float*)d_in[8];
    const float* be2 = (const float*)d_in[9];
    const float* W3 = (const float*)d_in[10];
    const float* b3 = (const float*)d_in[11];
    float* out = (float*)d_out;

    void *p_X1, *p_H, *p_HE, *p_Xs, *p_Ws, *p_nd_cnt, *p_he_cnt, *p_sum, *p_sumsq;
    cudaGetSymbolAddress(&p_X1, g_X1);
    cudaGetSymbolAddress(&p_H, g_H);
    cudaGetSymbolAddress(&p_HE, g_HE);
    cudaGetSymbolAddress(&p_Xs, g_Xs);
    cudaGetSymbolAddress(&p_Ws, g_Ws);
    cudaGetSymbolAddress(&p_nd_cnt, g_nd_cnt);
    cudaGetSymbolAddress(&p_he_cnt, g_he_cnt);
    cudaGetSymbolAddress(&p_sum, g_sum);
    cudaGetSymbolAddress(&p_sumsq, g_sumsq);
    float* X1 = (float*)p_X1;
    float* H  = (float*)p_H;
    float* HE = (float*)p_HE;
    __nv_bfloat16* Xs = (__nv_bfloat16*)p_Xs;
    __nv_bfloat16* Ws = (__nv_bfloat16*)p_Ws;

    void *p_nd_off, *p_he_off;
    cudaGetSymbolAddress(&p_nd_off, g_nd_off);
    cudaGetSymbolAddress(&p_he_off, g_he_off);

    const int GEMM_SMEM = 65536;
    cudaFuncSetAttribute(gemm_bf16_mma, cudaFuncAttributeMaxDynamicSharedMemorySize, GEMM_SMEM);
    const int mtiles = (N_NODES + 127) / 128;   // 782

    // ---- CSR build ----
    cudaMemsetAsync(p_nd_cnt, 0, N_NODES * sizeof(int));
    cudaMemsetAsync(p_he_cnt, 0, N_HE * sizeof(int));
    k_hist<<<(N_INC + 255) / 256, 256>>>(node_idx, he_idx);
    k_scan<<<1, 1024>>>((const int*)p_nd_cnt, (int*)p_nd_off, N_NODES);
    k_scan<<<1, 1024>>>((const int*)p_he_cnt, (int*)p_he_off, N_HE);
    cudaMemsetAsync(p_nd_cnt, 0, N_NODES * sizeof(int));
    cudaMemsetAsync(p_he_cnt, 0, N_HE * sizeof(int));
    k_scatter<<<(N_INC + 255) / 256, 256>>>(node_idx, he_idx);

    const int bn_grid = (N_NODES + BN_ROWS_PER_BLOCK - 1) / BN_ROWS_PER_BLOCK;
    const int apply_grid = (N_NODES * (HID / 4) + 255) / 256;

    // ---- layer 1: A(x W1) + b1 = (A x) W1 + b1 ; aggregate FIRST at 128 dims ----
    {
        k_he_gather<<<N_HE, IN_CH / 4>>>(x, HE, IN_CH / 4);
        k_node_gather<<<N_NODES, IN_CH / 4>>>(HE, nullptr, X1, IN_CH / 4);   // AX -> X1
        k_split_X<<<(N_NODES * (IN_CH / 2) + 255) / 256, 256>>>(X1, Xs, IN_CH);
        k_split_W<<<(IN_CH * HID + 255) / 256, 256>>>(W1, Ws, IN_CH, HID);
        dim3 grid(HID / 128, mtiles);
        gemm_bf16_mma<<<grid, 256, GEMM_SMEM>>>(Xs, Ws, X1, N_NODES, 3 * IN_CH, HID, b1, 1);
        cudaMemsetAsync(p_sum, 0, HID * sizeof(float));
        cudaMemsetAsync(p_sumsq, 0, HID * sizeof(float));
        k_bn_stats<<<bn_grid, HID>>>(X1);
        k_bn_apply<<<apply_grid, 256>>>(X1, H, g1, be1);
    }
    // ---- layer 2 ----
    {
        k_split_X<<<(N_NODES * (HID / 2) + 255) / 256, 256>>>(H, Xs, HID);
        k_split_W<<<(HID * HID + 255) / 256, 256>>>(W2, Ws, HID, HID);
        dim3 grid(HID / 128, mtiles);
        gemm_bf16_mma<<<grid, 256, GEMM_SMEM>>>(Xs, Ws, X1, N_NODES, 3 * HID, HID, nullptr, 0);
        k_he_gather<<<N_HE, HID / 4>>>(X1, HE, HID / 4);
        k_node_gather<<<N_NODES, HID / 4>>>(HE, b2, X1, HID / 4);
        cudaMemsetAsync(p_sum, 0, HID * sizeof(float));
        cudaMemsetAsync(p_sumsq, 0, HID * sizeof(float));
        k_bn_stats<<<bn_grid, HID>>>(X1);
        k_bn_apply<<<apply_grid, 256>>>(X1, H, g2, be2);
    }
    // ---- layer 3 ----
    {
        k_split_X<<<(N_NODES * (HID / 2) + 255) / 256, 256>>>(H, Xs, HID);
        k_split_W<<<(HID * OUT_CH + 255) / 256, 256>>>(W3, Ws, HID, OUT_CH);
        dim3 grid(OUT_CH / 128, mtiles);
        gemm_bf16_mma<<<grid, 256, GEMM_SMEM>>>(Xs, Ws, X1, N_NODES, 3 * HID, OUT_CH, nullptr, 0);
        k_he_gather<<<N_HE, OUT_CH / 4>>>(X1, HE, OUT_CH / 4);
        k_node_gather<<<N_NODES, OUT_CH / 4>>>(HE, b3, out, OUT_CH / 4);
    }
}